// round 15
// baseline (speedup 1.0000x reference)
#include <cuda_runtime.h>
#include <cuda_bf16.h>
#include <math.h>
#include <stdint.h>

#define B_ 2
#define T_ 256
#define S_ 6
#define F_ 64
#define D_ 512
#define H_ 8
#define HD_ 64
#define DFF_ 2048
#define NL_ 6
#define P_ 5
#define SEQ_PER_ 257
#define LT_ 1542
#define M_ 3084
#define SQRT_D 22.62741699796952f

#define QT_ 4
#define NQT_ ((LT_ + QT_ - 1) / QT_)   // 386

// ---------------- scratch (device globals; no allocations allowed) -------------
__device__ float g_h [M_ * D_];
__device__ float g_q [M_ * D_];
__device__ float g_k [M_ * D_];
__device__ float g_v [M_ * D_];
__device__ __nv_bfloat16 g_qp[M_ * D_]; // [b][h][l'][hd] bf16
__device__ __nv_bfloat16 g_kT[M_ * D_]; // [b][h][hd][l'] bf16
__device__ float g_xa[M_ * D_];
__device__ float g_ffn[M_ * 2 * DFF_];
__device__ float g_cos[T_ * 32];
__device__ float g_sin[T_ * 32];
// bf16 split planes for GEMM A operands (shared: h -> o -> h -> act -> h ...)
__device__ __nv_bfloat16 g_ah[M_ * DFF_];
__device__ __nv_bfloat16 g_al[M_ * DFF_];
// pair-packed bf16 hi/lo weights, per layer: [WQ|WK|WV|WO|WIN|WFF]
#define WPAIR_L 2097152
#define OFF_WQ  0
#define OFF_WK  131072
#define OFF_WV  262144
#define OFF_WO  393216
#define OFF_WIN 524288
#define OFF_WFF 1572864
__device__ uint32_t g_wh[WPAIR_L * NL_];
__device__ uint32_t g_wl[WPAIR_L * NL_];

__device__ __forceinline__ void split_store(float v, __nv_bfloat16* hi, __nv_bfloat16* lo,
                                            size_t idx) {
    __nv_bfloat16 h = __float2bfloat16(v);
    hi[idx] = h;
    lo[idx] = __float2bfloat16(v - __bfloat162float(h));
}

// ---------------- rope table (matches numpy float64 precompute) ----------------
__global__ void rope_init_kernel() {
    int i = blockIdx.x * blockDim.x + threadIdx.x;
    if (i >= T_ * 32) return;
    int t = i >> 5, j = i & 31;
    double freq = pow(10000.0, -(double)j / 32.0);
    double ramp = (double)j / 13.0;
    if (ramp > 1.0) ramp = 1.0;
    if (ramp < 0.0) ramp = 0.0;
    double f = freq / 40.0 * ramp + freq * (1.0 - ramp);
    double ang = (double)t * f;
    g_cos[i] = (float)cos(ang);
    g_sin[i] = (float)sin(ang);
}

// ---------------- weight split: pair-packed bf16 hi/lo, all layers --------------
__global__ void split_w_all(const float* __restrict__ W, uint32_t* __restrict__ hi,
                            uint32_t* __restrict__ lo, int K, int N, int off) {
    int per = (K >> 1) * N;
    int total = NL_ * per;
    for (int idx = blockIdx.x * blockDim.x + threadIdx.x; idx < total;
         idx += gridDim.x * blockDim.x) {
        int layer = idx / per, r = idx - layer * per;
        int kp = r / N, n = r - kp * N;
        const float* src = W + (size_t)layer * K * N;
        float x0 = src[(size_t)(2 * kp) * N + n];
        float x1 = src[(size_t)(2 * kp + 1) * N + n];
        __nv_bfloat16 h0 = __float2bfloat16(x0);
        __nv_bfloat16 h1 = __float2bfloat16(x1);
        __nv_bfloat16 l0 = __float2bfloat16(x0 - __bfloat162float(h0));
        __nv_bfloat16 l1 = __float2bfloat16(x1 - __bfloat162float(h1));
        size_t dst = (size_t)layer * WPAIR_L + off + r;
        hi[dst] = ((unsigned)__bfloat16_as_ushort(h1) << 16) | (unsigned)__bfloat16_as_ushort(h0);
        lo[dst] = ((unsigned)__bfloat16_as_ushort(l1) << 16) | (unsigned)__bfloat16_as_ushort(l0);
    }
}

// ---------------- embedding + first cosine norm (+ h planes) -------------------
__global__ void embed_kernel(const float* __restrict__ x, const int* __restrict__ sep_idx,
                             const int* __restrict__ tick_idx, const float* __restrict__ sep_emb,
                             const float* __restrict__ tick_emb, const float* __restrict__ shared_W,
                             const float* __restrict__ unique_W,
                             __nv_bfloat16* __restrict__ hh, __nv_bfloat16* __restrict__ hl) {
    int bid = blockIdx.x;
    int s = bid % S_;
    int t = (bid / S_) % SEQ_PER_;
    int b = bid / (S_ * SEQ_PER_);
    int tid = threadIdx.x;
    __shared__ float xrow[F_];
    __shared__ float red[256];
    if (t > 0 && tid < F_)
        xrow[tid] = x[(((size_t)(b * T_ + (t - 1)) * S_) + s) * F_ + tid];
    __syncthreads();
    int tk = tick_idx[b * S_ + s];
    float vals[2];
#pragma unroll
    for (int ii = 0; ii < 2; ii++) {
        int d = tid + ii * 256;
        float a;
        if (t == 0) {
            a = sep_emb[sep_idx[b] * D_ + d];
        } else {
            a = 0.f;
            if (d < 384) {
#pragma unroll 8
                for (int f = 0; f < F_; f++) a += xrow[f] * shared_W[f * 384 + d];
            } else {
#pragma unroll 8
                for (int f = 0; f < F_; f++) a += xrow[f] * unique_W[(s * F_ + f) * 128 + (d - 384)];
            }
        }
        a += tick_emb[tk * D_ + d];
        vals[ii] = a;
    }
    red[tid] = vals[0] * vals[0] + vals[1] * vals[1];
    __syncthreads();
    for (int st = 128; st > 0; st >>= 1) { if (tid < st) red[tid] += red[tid + st]; __syncthreads(); }
    float scale = 1.f / fmaxf(sqrtf(red[0]), 1e-6f);
    size_t rowo = ((size_t)(b * LT_) + t * S_ + s) * D_;
    float h0 = vals[0] * scale, h1 = vals[1] * scale;
    g_h[rowo + tid] = h0;
    g_h[rowo + tid + 256] = h1;
    split_store(h0, hh, hl, rowo + tid);
    split_store(h1, hh, hl, rowo + tid + 256);
}

// ---------------- bf16x3 tensor-core GEMM (pre-split operands) ------------------
// acc += Al*Bh + Ah*Bl + Ah*Bh via m16n8k16 bf16 MMA; BM=128, BN=64, BK=16;
// 256 threads = 8 warps (4Mx2N), 32x32 warp tile; SMEM uint2{hi_pair, lo_pair},
// swizzle row ^= (kpair&1)<<4; strides 132/68 uint2.
#define ASTR 132
#define BSTR 68

__device__ __forceinline__ void mma_bf16(float* d, const unsigned* a, const unsigned* b) {
    asm volatile(
        "mma.sync.aligned.m16n8k16.row.col.f32.bf16.bf16.f32 "
        "{%0,%1,%2,%3},{%4,%5,%6,%7},{%8,%9},{%0,%1,%2,%3};"
        : "+f"(d[0]), "+f"(d[1]), "+f"(d[2]), "+f"(d[3])
        : "r"(a[0]), "r"(a[1]), "r"(a[2]), "r"(a[3]), "r"(b[0]), "r"(b[1]));
}

__device__ __forceinline__ void gemm_core(const __nv_bfloat16* __restrict__ Ah,
                                          const __nv_bfloat16* __restrict__ Al,
                                          const uint32_t* __restrict__ Bhp,
                                          const uint32_t* __restrict__ Blp,
                                          float* __restrict__ C,
                                          int Mdim, int Kdim, int Ndim,
                                          int m0, int n0) {
    __shared__ __align__(16) uint2 As2[2][8][ASTR];
    __shared__ __align__(16) uint2 Bs2[2][8][BSTR];

    int tid = threadIdx.x;
    int lane = tid & 31, wid = tid >> 5;
    int wm = (wid & 3) * 32;
    int wn = (wid >> 2) * 32;
    int gid = lane >> 2, tig = lane & 3;
    int sA = (tig & 1) << 4;

    int rA = tid >> 1;
    int halfA = tid & 1;
    int kpB = tid >> 5;
    int ncB = lane * 2;
    int scB = ncB ^ ((kpB & 1) << 4);

    uint4 a_hi, a_lo;
    uint2 b_hi, b_lo;

    float acc[2][4][4];
#pragma unroll
    for (int i = 0; i < 2; i++)
#pragma unroll
        for (int j = 0; j < 4; j++)
#pragma unroll
            for (int k = 0; k < 4; k++) acc[i][j][k] = 0.f;

    int nk = Kdim >> 4;
    int growA = m0 + rA;
    bool aok = (growA < Mdim);
    size_t arow = (size_t)growA * Kdim;
    size_t brow = (size_t)kpB * Ndim + n0 + ncB;

    if (aok) {
        a_hi = *(const uint4*)(Ah + arow + halfA * 8);
        a_lo = *(const uint4*)(Al + arow + halfA * 8);
    } else {
        a_hi = make_uint4(0u, 0u, 0u, 0u); a_lo = a_hi;
    }
    b_hi = *(const uint2*)(Bhp + brow);
    b_lo = *(const uint2*)(Blp + brow);
    {
        int kp0 = halfA * 4;
        int rs0 = rA;
        int rs1 = rA ^ 16;
        As2[0][kp0 + 0][rs0] = make_uint2(a_hi.x, a_lo.x);
        As2[0][kp0 + 1][rs1] = make_uint2(a_hi.y, a_lo.y);
        As2[0][kp0 + 2][rs0] = make_uint2(a_hi.z, a_lo.z);
        As2[0][kp0 + 3][rs1] = make_uint2(a_hi.w, a_lo.w);
        *(uint4*)&Bs2[0][kpB][scB] = make_uint4(b_hi.x, b_lo.x, b_hi.y, b_lo.y);
    }
    __syncthreads();

    int cur = 0;
    for (int ks = 0; ks < nk; ks++) {
        int k0n = (ks + 1) << 4;
        if (ks + 1 < nk) {
            if (aok) {
                a_hi = *(const uint4*)(Ah + arow + k0n + halfA * 8);
                a_lo = *(const uint4*)(Al + arow + k0n + halfA * 8);
            }
            size_t bo = (size_t)(k0n >> 1) * Ndim;
            b_hi = *(const uint2*)(Bhp + bo + brow);
            b_lo = *(const uint2*)(Blp + bo + brow);
        }

        {
            unsigned afH[2][4], afL[2][4], bfH[4][2], bfL[4][2];
#pragma unroll
            for (int ma = 0; ma < 2; ma++) {
                int mr = wm + ma * 16 + gid;
                uint2 v0 = As2[cur][tig][mr ^ sA];
                uint2 v1 = As2[cur][tig][(mr + 8) ^ sA];
                uint2 v2 = As2[cur][tig + 4][mr ^ sA];
                uint2 v3 = As2[cur][tig + 4][(mr + 8) ^ sA];
                afH[ma][0] = v0.x; afL[ma][0] = v0.y;
                afH[ma][1] = v1.x; afL[ma][1] = v1.y;
                afH[ma][2] = v2.x; afL[ma][2] = v2.y;
                afH[ma][3] = v3.x; afL[ma][3] = v3.y;
            }
#pragma unroll
            for (int nb = 0; nb < 4; nb++) {
                int nc = wn + nb * 8 + gid;
                uint2 u0 = Bs2[cur][tig][nc ^ sA];
                uint2 u1 = Bs2[cur][tig + 4][nc ^ sA];
                bfH[nb][0] = u0.x; bfL[nb][0] = u0.y;
                bfH[nb][1] = u1.x; bfL[nb][1] = u1.y;
            }
#pragma unroll
            for (int ma = 0; ma < 2; ma++)
#pragma unroll
                for (int nb = 0; nb < 4; nb++) {
                    mma_bf16(acc[ma][nb], afL[ma], bfH[nb]);
                    mma_bf16(acc[ma][nb], afH[ma], bfL[nb]);
                    mma_bf16(acc[ma][nb], afH[ma], bfH[nb]);
                }
        }

        if (ks + 1 < nk) {
            int nxt = cur ^ 1;
            int kp0 = halfA * 4;
            int rs0 = rA;
            int rs1 = rA ^ 16;
            As2[nxt][kp0 + 0][rs0] = make_uint2(a_hi.x, a_lo.x);
            As2[nxt][kp0 + 1][rs1] = make_uint2(a_hi.y, a_lo.y);
            As2[nxt][kp0 + 2][rs0] = make_uint2(a_hi.z, a_lo.z);
            As2[nxt][kp0 + 3][rs1] = make_uint2(a_hi.w, a_lo.w);
            *(uint4*)&Bs2[nxt][kpB][scB] = make_uint4(b_hi.x, b_lo.x, b_hi.y, b_lo.y);
        }
        __syncthreads();
        cur ^= 1;
    }

#pragma unroll
    for (int ma = 0; ma < 2; ma++) {
#pragma unroll
        for (int nb = 0; nb < 4; nb++) {
            int row = m0 + wm + ma * 16 + gid;
            int col = n0 + wn + nb * 8 + tig * 2;
            if (row < Mdim) {
                float2 v = make_float2(acc[ma][nb][0], acc[ma][nb][1]);
                *(float2*)(C + (size_t)row * Ndim + col) = v;
            }
            if (row + 8 < Mdim) {
                float2 v = make_float2(acc[ma][nb][2], acc[ma][nb][3]);
                *(float2*)(C + (size_t)(row + 8) * Ndim + col) = v;
            }
        }
    }
}

__global__ __launch_bounds__(256, 2)
void gemm_kernel(const __nv_bfloat16* __restrict__ Ah, const __nv_bfloat16* __restrict__ Al,
                 const uint32_t* __restrict__ Bhp, const uint32_t* __restrict__ Blp,
                 float* __restrict__ C, int Mdim, int Kdim, int Ndim) {
    gemm_core(Ah, Al, Bhp, Blp, C, Mdim, Kdim, Ndim, blockIdx.y * 128, blockIdx.x * 64);
}

// fused Q/K/V projection: blockIdx.x 0..23 -> (which, n-block)
__global__ __launch_bounds__(256, 2)
void gemm_qkv_kernel(const __nv_bfloat16* __restrict__ Ah, const __nv_bfloat16* __restrict__ Al,
                     const uint32_t* __restrict__ whp, const uint32_t* __restrict__ wlp,
                     float* __restrict__ Cq, float* __restrict__ Ck, float* __restrict__ Cv) {
    int which = blockIdx.x >> 3;
    int n0 = (blockIdx.x & 7) * 64;
    const uint32_t* Bh = whp + (size_t)which * 131072;
    const uint32_t* Bl = wlp + (size_t)which * 131072;
    float* C = (which == 0) ? Cq : (which == 1) ? Ck : Cv;
    gemm_core(Ah, Al, Bh, Bl, C, M_, D_, D_, blockIdx.y * 128, n0);
}

// ---------------- q/k post: rope + transpose + cosine norm + scale -> bf16 ------
__global__ void qkpost_kernel(const float* __restrict__ qin, const float* __restrict__ kin,
                              __nv_bfloat16* __restrict__ qout, __nv_bfloat16* __restrict__ kout,
                              const float* __restrict__ sqk) {
    int transposed = blockIdx.y;
    const float* in = transposed ? kin : qin;
    __nv_bfloat16* out = transposed ? kout : qout;
    int wrk = blockIdx.x * 8 + (threadIdx.x >> 5);
    if (wrk >= B_ * LT_ * H_) return;
    int h = wrk % H_;
    int l = (wrk / H_) % LT_;
    int b = wrk / (H_ * LT_);
    int t = l / S_, s = l % S_;
    int j = threadIdx.x & 31;
    const float* row = in + ((size_t)(b * LT_) + l) * D_ + h * HD_;
    float x0 = row[2 * j], x1 = row[2 * j + 1];
    float y0 = x0, y1 = x1;
    if (t > 0) {
        float c = g_cos[(t - 1) * 32 + j], sn = g_sin[(t - 1) * 32 + j];
        y0 = x0 * c - x1 * sn;
        y1 = x0 * sn + x1 * c;
    }
    float ss = y0 * y0 + y1 * y1;
#pragma unroll
    for (int o = 16; o > 0; o >>= 1) ss += __shfl_xor_sync(0xffffffffu, ss, o);
    float scale = 0.125f / fmaxf(sqrtf(ss), 1e-6f);
    int lp = s * SEQ_PER_ + t;
    float o0 = y0 * scale * sqk[h * HD_ + 2 * j];
    float o1 = y1 * scale * sqk[h * HD_ + 2 * j + 1];
    if (transposed) {
        size_t base = (size_t)(b * H_ + h) * HD_ * LT_;
        out[base + (size_t)(2 * j) * LT_ + lp] = __float2bfloat16(o0);
        out[base + (size_t)(2 * j + 1) * LT_ + lp] = __float2bfloat16(o1);
    } else {
        __nv_bfloat16* orow = out + ((size_t)((b * H_ + h) * LT_) + lp) * HD_;
        orow[2 * j] = __float2bfloat16(o0);
        orow[2 * j + 1] = __float2bfloat16(o1);
    }
}

// ---------------- attention: q-tile of 4 rows, fused exp softmax, bf16 q/k -----
// Output written directly as bf16 hi/lo planes (feeds the Wo GEMM).
__global__ void attn_kernel(const __nv_bfloat16* __restrict__ qp,
                            const __nv_bfloat16* __restrict__ kT,
                            const float* __restrict__ vv,
                            __nv_bfloat16* __restrict__ oh, __nv_bfloat16* __restrict__ ol) {
    int bid = blockIdx.x;
    int qt = bid % NQT_;
    int h = (bid / NQT_) % H_;
    int b = bid / (NQT_ * H_);
    int q0 = qt * QT_;
    int tid = threadIdx.x;
    int wid = tid >> 5, lane = tid & 31;

    __shared__ __align__(16) float qs[QT_][HD_];
    __shared__ float sc[QT_][LT_];
    __shared__ float wsum[QT_][8];
    __shared__ float part[8][QT_][HD_];
    __shared__ float sinv[QT_];

    for (int i = tid; i < QT_ * HD_; i += 256) {
        int qi = i >> 6, d = i & 63;
        int ql = q0 + qi;
        qs[qi][d] = (ql < LT_)
                    ? __bfloat162float(qp[((size_t)((b * H_ + h) * LT_) + ql) * HD_ + d])
                    : 0.f;
    }
    __syncthreads();

    const __nv_bfloat16* kbase = kT + (size_t)(b * H_ + h) * HD_ * LT_;
    int tq0 = (q0 + 0) % SEQ_PER_;
    int tq1 = (q0 + 1) % SEQ_PER_;
    int tq2 = (q0 + 2) % SEQ_PER_;
    int tq3 = (q0 + 3) % SEQ_PER_;
    int tqa = (tq0 > tq1) ? tq0 : tq1;
    int tqb = (tq2 > tq3) ? tq2 : tq3;
    int tqmax = (tqa > tqb) ? tqa : tqb;

    float ls0 = 0.f, ls1 = 0.f, ls2 = 0.f, ls3 = 0.f;
    for (int k = tid; k < LT_; k += 256) {
        int tk = k % SEQ_PER_;
        if (tk > tqmax) {
            sc[0][k] = 0.f; sc[1][k] = 0.f; sc[2][k] = 0.f; sc[3][k] = 0.f;
            continue;
        }
        float a0 = 0.f, a1 = 0.f, a2 = 0.f, a3 = 0.f;
#pragma unroll 4
        for (int d4 = 0; d4 < HD_; d4 += 4) {
            float k0 = __bfloat162float(kbase[(size_t)(d4 + 0) * LT_ + k]);
            float k1 = __bfloat162float(kbase[(size_t)(d4 + 1) * LT_ + k]);
            float k2 = __bfloat162float(kbase[(size_t)(d4 + 2) * LT_ + k]);
            float k3 = __bfloat162float(kbase[(size_t)(d4 + 3) * LT_ + k]);
            float4 v0 = *(const float4*)&qs[0][d4];
            float4 v1 = *(const float4*)&qs[1][d4];
            float4 v2 = *(const float4*)&qs[2][d4];
            float4 v3 = *(const float4*)&qs[3][d4];
            a0 += v0.x * k0 + v0.y * k1 + v0.z * k2 + v0.w * k3;
            a1 += v1.x * k0 + v1.y * k1 + v1.z * k2 + v1.w * k3;
            a2 += v2.x * k0 + v2.y * k1 + v2.z * k2 + v2.w * k3;
            a3 += v3.x * k0 + v3.y * k1 + v3.z * k2 + v3.w * k3;
        }
        float e0 = (tk <= tq0) ? expf(a0 * 8.f) : 0.f;
        float e1 = (tk <= tq1) ? expf(a1 * 8.f) : 0.f;
        float e2 = (tk <= tq2) ? expf(a2 * 8.f) : 0.f;
        float e3 = (tk <= tq3) ? expf(a3 * 8.f) : 0.f;
        sc[0][k] = e0; sc[1][k] = e1; sc[2][k] = e2; sc[3][k] = e3;
        ls0 += e0; ls1 += e1; ls2 += e2; ls3 += e3;
    }
#pragma unroll
    for (int o = 16; o > 0; o >>= 1) {
        ls0 += __shfl_xor_sync(0xffffffffu, ls0, o);
        ls1 += __shfl_xor_sync(0xffffffffu, ls1, o);
        ls2 += __shfl_xor_sync(0xffffffffu, ls2, o);
        ls3 += __shfl_xor_sync(0xffffffffu, ls3, o);
    }
    if (lane == 0) {
        wsum[0][wid] = ls0; wsum[1][wid] = ls1;
        wsum[2][wid] = ls2; wsum[3][wid] = ls3;
    }
    __syncthreads();
    if (tid < 32) {
        int qi = tid >> 3, w = tid & 7;
        float v = wsum[qi][w];
        v += __shfl_xor_sync(0xffffffffu, v, 4);
        v += __shfl_xor_sync(0xffffffffu, v, 2);
        v += __shfl_xor_sync(0xffffffffu, v, 1);
        if (w == 0) sinv[qi] = 1.f / v;
    }
    __syncthreads();

    float acc[QT_][2] = {};
    const float* vbase = vv + (size_t)b * LT_ * D_ + h * HD_;
    for (int k = wid; k < LT_; k += 8) {
        float p0 = sc[0][k], p1 = sc[1][k], p2 = sc[2][k], p3 = sc[3][k];
        if (p0 == 0.f && p1 == 0.f && p2 == 0.f && p3 == 0.f) continue;
        float v0 = vbase[(size_t)k * D_ + lane];
        float v1 = vbase[(size_t)k * D_ + lane + 32];
        acc[0][0] += p0 * v0; acc[0][1] += p0 * v1;
        acc[1][0] += p1 * v0; acc[1][1] += p1 * v1;
        acc[2][0] += p2 * v0; acc[2][1] += p2 * v1;
        acc[3][0] += p3 * v0; acc[3][1] += p3 * v1;
    }
#pragma unroll
    for (int qi = 0; qi < QT_; qi++) {
        part[wid][qi][lane] = acc[qi][0];
        part[wid][qi][lane + 32] = acc[qi][1];
    }
    __syncthreads();
    {
        int qi = tid >> 6, d = tid & 63;
        float o = 0.f;
#pragma unroll
        for (int w = 0; w < 8; w++) o += part[w][qi][d];
        int ql = q0 + qi;
        if (ql < LT_) {
            size_t oidx = ((size_t)(b * LT_) + ql) * D_ + h * HD_ + d;
            split_store(o * sinv[qi], oh, ol, oidx);
        }
    }
}

// ---------------- residual: h = cn(h + eig*sqrt(D)*(cn(xa) - h)) (+ planes) ----
__global__ void resid_kernel(const float* __restrict__ xa, const float* __restrict__ eig,
                             __nv_bfloat16* __restrict__ hh, __nv_bfloat16* __restrict__ hl) {
    int row = blockIdx.x, tid = threadIdx.x;
    __shared__ float red[256];
    size_t off = (size_t)row * D_;
    float x0 = xa[off + tid], x1 = xa[off + tid + 256];
    red[tid] = x0 * x0 + x1 * x1;
    __syncthreads();
    for (int st = 128; st > 0; st >>= 1) { if (tid < st) red[tid] += red[tid + st]; __syncthreads(); }
    float s1 = 1.f / fmaxf(sqrtf(red[0]), 1e-6f);
    __syncthreads();
    float h0 = g_h[off + tid], h1 = g_h[off + tid + 256];
    float t0 = h0 + eig[tid] * SQRT_D * (x0 * s1 - h0);
    float t1 = h1 + eig[tid + 256] * SQRT_D * (x1 * s1 - h1);
    red[tid] = t0 * t0 + t1 * t1;
    __syncthreads();
    for (int st = 128; st > 0; st >>= 1) { if (tid < st) red[tid] += red[tid + st]; __syncthreads(); }
    float s2 = 1.f / fmaxf(sqrtf(red[0]), 1e-6f);
    float n0 = t0 * s2, n1 = t1 * s2;
    g_h[off + tid] = n0;
    g_h[off + tid + 256] = n1;
    split_store(n0, hh, hl, off + tid);
    split_store(n1, hh, hl, off + tid + 256);
}

// ---------------- FFN activation -> bf16 planes --------------------------------
__global__ void act_kernel(const float* __restrict__ g, const float* __restrict__ su,
                           const float* __restrict__ sv,
                           __nv_bfloat16* __restrict__ oh, __nv_bfloat16* __restrict__ ol) {
    int total = M_ * DFF_;
    for (int idx = blockIdx.x * blockDim.x + threadIdx.x; idx < total;
         idx += gridDim.x * blockDim.x) {
        int row = idx / DFF_, j = idx - row * DFF_;
        float u = g[(size_t)row * (2 * DFF_) + j];
        float v = g[(size_t)row * (2 * DFF_) + DFF_ + j];
        float vs = v * sv[j] * SQRT_D;
        float sig = 1.f / (1.f + expf(-vs));
        split_store(u * su[j] * vs * sig, oh, ol, idx);
    }
}

// ---------------- output head: out = h @ Wout * (s_z * sqrt(D)) ----------------
__global__ void out_kernel(const float* __restrict__ Wout, const float* __restrict__ s_z,
                           float* __restrict__ out) {
    int row = blockIdx.x, tid = threadIdx.x;
    __shared__ float hs[D_];
    hs[tid] = g_h[(size_t)row * D_ + tid];
    hs[tid + 256] = g_h[(size_t)row * D_ + tid + 256];
    __syncthreads();
    int w = tid >> 5, lane = tid & 31;
    if (w < P_) {
        float a = 0.f;
        for (int d = lane; d < D_; d += 32) a += hs[d] * Wout[d * P_ + w];
#pragma unroll
        for (int o = 16; o > 0; o >>= 1) a += __shfl_xor_sync(0xffffffffu, a, o);
        if (lane == 0) out[row * P_ + w] = a * s_z[w] * SQRT_D;
    }
}

// ---------------- host driver --------------------------------------------------
extern "C" void kernel_launch(void* const* d_in, const int* in_sizes, int n_in,
                              void* d_out, int out_size) {
    (void)in_sizes; (void)n_in; (void)out_size;
    const float* x        = (const float*)d_in[0];
    const int*   sep      = (const int*)  d_in[1];
    const int*   tick     = (const int*)  d_in[2];
    const float* sep_emb  = (const float*)d_in[3];
    const float* tick_emb = (const float*)d_in[4];
    const float* shared_W = (const float*)d_in[5];
    const float* unique_W = (const float*)d_in[6];
    const float* Wq       = (const float*)d_in[7];
    const float* Wk       = (const float*)d_in[8];
    const float* Wv       = (const float*)d_in[9];
    const float* Wo       = (const float*)d_in[10];
    const float* s_qk     = (const float*)d_in[11];
    const float* Win      = (const float*)d_in[12];
    const float* Wff      = (const float*)d_in[13];
    const float* s_u      = (const float*)d_in[14];
    const float* s_v      = (const float*)d_in[15];
    const float* eigen_a  = (const float*)d_in[16];
    const float* eigen_m  = (const float*)d_in[17];
    const float* Wout     = (const float*)d_in[18];
    const float* s_z      = (const float*)d_in[19];
    float* out = (float*)d_out;

    float *p_h, *p_q, *p_k, *p_v, *p_xa, *p_ffn;
    __nv_bfloat16 *p_qp, *p_kT, *p_ah, *p_al;
    uint32_t *p_wh, *p_wl;
    cudaGetSymbolAddress((void**)&p_h,  g_h);
    cudaGetSymbolAddress((void**)&p_q,  g_q);
    cudaGetSymbolAddress((void**)&p_k,  g_k);
    cudaGetSymbolAddress((void**)&p_v,  g_v);
    cudaGetSymbolAddress((void**)&p_qp, g_qp);
    cudaGetSymbolAddress((void**)&p_kT, g_kT);
    cudaGetSymbolAddress((void**)&p_xa, g_xa);
    cudaGetSymbolAddress((void**)&p_ffn, g_ffn);
    cudaGetSymbolAddress((void**)&p_ah, g_ah);
    cudaGetSymbolAddress((void**)&p_al, g_al);
    cudaGetSymbolAddress((void**)&p_wh, g_wh);
    cudaGetSymbolAddress((void**)&p_wl, g_wl);

    rope_init_kernel<<<32, 256>>>();
    split_w_all<<<1024, 256>>>(Wq,  p_wh, p_wl, 512, 512,  OFF_WQ);
    split_w_all<<<1024, 256>>>(Wk,  p_wh, p_wl, 512, 512,  OFF_WK);
    split_w_all<<<1024, 256>>>(Wv,  p_wh, p_wl, 512, 512,  OFF_WV);
    split_w_all<<<1024, 256>>>(Wo,  p_wh, p_wl, 512, 512,  OFF_WO);
    split_w_all<<<4096, 256>>>(Win, p_wh, p_wl, 512, 4096, OFF_WIN);
    split_w_all<<<4096, 256>>>(Wff, p_wh, p_wl, 2048, 512, OFF_WFF);

    embed_kernel<<<B_ * SEQ_PER_ * S_, 256>>>(x, sep, tick, sep_emb, tick_emb,
                                              shared_W, unique_W, p_ah, p_al);

    dim3 gqkv(24, (M_ + 127) / 128);
    dim3 g512(8, (M_ + 127) / 128);
    dim3 g4096(64, (M_ + 127) / 128);
    dim3 gqkpost((B_ * LT_ * H_ + 7) / 8, 2);

    for (int L = 0; L < NL_; L++) {
        size_t wo = (size_t)L * WPAIR_L;
        gemm_qkv_kernel<<<gqkv, 256>>>(p_ah, p_al, p_wh + wo + OFF_WQ, p_wl + wo + OFF_WQ,
                                       p_q, p_k, p_v);
        qkpost_kernel<<<gqkpost, 256>>>(p_q, p_k, p_qp, p_kT, s_qk + L * H_ * HD_);
        attn_kernel<<<B_ * H_ * NQT_, 256>>>(p_qp, p_kT, p_v, p_ah, p_al);
        gemm_kernel<<<g512, 256>>>(p_ah, p_al, p_wh + wo + OFF_WO, p_wl + wo + OFF_WO,
                                   p_xa, M_, D_, D_);
        resid_kernel<<<M_, 256>>>(p_xa, eigen_a + L * D_, p_ah, p_al);
        gemm_kernel<<<g4096, 256>>>(p_ah, p_al, p_wh + wo + OFF_WIN, p_wl + wo + OFF_WIN,
                                    p_ffn, M_, D_, 2 * DFF_);
        act_kernel<<<2048, 256>>>(p_ffn, s_u + L * DFF_, s_v + L * DFF_, p_ah, p_al);
        gemm_kernel<<<g512, 256>>>(p_ah, p_al, p_wh + wo + OFF_WFF, p_wl + wo + OFF_WFF,
                                   p_xa, M_, DFF_, 512);
        resid_kernel<<<M_, 256>>>(p_xa, eigen_m + L * D_, p_ah, p_al);
    }
    out_kernel<<<M_, 256>>>(Wout, s_z, out);
}

// round 17
// speedup vs baseline: 1.0794x; 1.0794x over previous
#include <cuda_runtime.h>
#include <cuda_bf16.h>
#include <math.h>
#include <stdint.h>

#define B_ 2
#define T_ 256
#define S_ 6
#define F_ 64
#define D_ 512
#define H_ 8
#define HD_ 64
#define DFF_ 2048
#define NL_ 6
#define P_ 5
#define SEQ_PER_ 257
#define LT_ 1542
#define M_ 3084
#define SQRT_D 22.62741699796952f

#define QT_ 4
#define NQT_ ((LT_ + QT_ - 1) / QT_)   // 386
#define LTH_ (LT_ / 2)                 // 771 key pairs

// ---------------- scratch (device globals; no allocations allowed) -------------
__device__ float g_h [M_ * D_];
__device__ float g_q [M_ * D_];
__device__ float g_k [M_ * D_];
__device__ float g_v [M_ * D_];
__device__ __nv_bfloat16 g_qp[M_ * D_]; // [b][h][l'][hd] bf16
__device__ __nv_bfloat16 g_kT[M_ * D_]; // [b][h][hd][l'] bf16
__device__ float g_xa[M_ * D_];
__device__ float g_ffn[M_ * 2 * DFF_];
__device__ float g_cos[T_ * 32];
__device__ float g_sin[T_ * 32];
// bf16 split planes for GEMM A operands (shared: h -> o -> h -> act -> h ...)
__device__ __nv_bfloat16 g_ah[M_ * DFF_];
__device__ __nv_bfloat16 g_al[M_ * DFF_];
// pair-packed bf16 hi/lo weights, per layer: [WQ|WK|WV|WO|WIN|WFF]
#define WPAIR_L 2097152
#define OFF_WQ  0
#define OFF_WK  131072
#define OFF_WV  262144
#define OFF_WO  393216
#define OFF_WIN 524288
#define OFF_WFF 1572864
__device__ uint32_t g_wh[WPAIR_L * NL_];
__device__ uint32_t g_wl[WPAIR_L * NL_];

__device__ __forceinline__ void split_store(float v, __nv_bfloat16* hi, __nv_bfloat16* lo,
                                            size_t idx) {
    __nv_bfloat16 h = __float2bfloat16(v);
    hi[idx] = h;
    lo[idx] = __float2bfloat16(v - __bfloat162float(h));
}

// ---------------- rope table (matches numpy float64 precompute) ----------------
__global__ void rope_init_kernel() {
    int i = blockIdx.x * blockDim.x + threadIdx.x;
    if (i >= T_ * 32) return;
    int t = i >> 5, j = i & 31;
    double freq = pow(10000.0, -(double)j / 32.0);
    double ramp = (double)j / 13.0;
    if (ramp > 1.0) ramp = 1.0;
    if (ramp < 0.0) ramp = 0.0;
    double f = freq / 40.0 * ramp + freq * (1.0 - ramp);
    double ang = (double)t * f;
    g_cos[i] = (float)cos(ang);
    g_sin[i] = (float)sin(ang);
}

// ---------------- weight split: pair-packed bf16 hi/lo, all layers --------------
__global__ void split_w_all(const float* __restrict__ W, uint32_t* __restrict__ hi,
                            uint32_t* __restrict__ lo, int K, int N, int off) {
    int per = (K >> 1) * N;
    int total = NL_ * per;
    for (int idx = blockIdx.x * blockDim.x + threadIdx.x; idx < total;
         idx += gridDim.x * blockDim.x) {
        int layer = idx / per, r = idx - layer * per;
        int kp = r / N, n = r - kp * N;
        const float* src = W + (size_t)layer * K * N;
        float x0 = src[(size_t)(2 * kp) * N + n];
        float x1 = src[(size_t)(2 * kp + 1) * N + n];
        __nv_bfloat16 h0 = __float2bfloat16(x0);
        __nv_bfloat16 h1 = __float2bfloat16(x1);
        __nv_bfloat16 l0 = __float2bfloat16(x0 - __bfloat162float(h0));
        __nv_bfloat16 l1 = __float2bfloat16(x1 - __bfloat162float(h1));
        size_t dst = (size_t)layer * WPAIR_L + off + r;
        hi[dst] = ((unsigned)__bfloat16_as_ushort(h1) << 16) | (unsigned)__bfloat16_as_ushort(h0);
        lo[dst] = ((unsigned)__bfloat16_as_ushort(l1) << 16) | (unsigned)__bfloat16_as_ushort(l0);
    }
}

// ---------------- embedding + first cosine norm (+ h planes) -------------------
__global__ void embed_kernel(const float* __restrict__ x, const int* __restrict__ sep_idx,
                             const int* __restrict__ tick_idx, const float* __restrict__ sep_emb,
                             const float* __restrict__ tick_emb, const float* __restrict__ shared_W,
                             const float* __restrict__ unique_W,
                             __nv_bfloat16* __restrict__ hh, __nv_bfloat16* __restrict__ hl) {
    int bid = blockIdx.x;
    int s = bid % S_;
    int t = (bid / S_) % SEQ_PER_;
    int b = bid / (S_ * SEQ_PER_);
    int tid = threadIdx.x;
    __shared__ float xrow[F_];
    __shared__ float red[256];
    if (t > 0 && tid < F_)
        xrow[tid] = x[(((size_t)(b * T_ + (t - 1)) * S_) + s) * F_ + tid];
    __syncthreads();
    int tk = tick_idx[b * S_ + s];
    float vals[2];
#pragma unroll
    for (int ii = 0; ii < 2; ii++) {
        int d = tid + ii * 256;
        float a;
        if (t == 0) {
            a = sep_emb[sep_idx[b] * D_ + d];
        } else {
            a = 0.f;
            if (d < 384) {
#pragma unroll 8
                for (int f = 0; f < F_; f++) a += xrow[f] * shared_W[f * 384 + d];
            } else {
#pragma unroll 8
                for (int f = 0; f < F_; f++) a += xrow[f] * unique_W[(s * F_ + f) * 128 + (d - 384)];
            }
        }
        a += tick_emb[tk * D_ + d];
        vals[ii] = a;
    }
    red[tid] = vals[0] * vals[0] + vals[1] * vals[1];
    __syncthreads();
    for (int st = 128; st > 0; st >>= 1) { if (tid < st) red[tid] += red[tid + st]; __syncthreads(); }
    float scale = 1.f / fmaxf(sqrtf(red[0]), 1e-6f);
    size_t rowo = ((size_t)(b * LT_) + t * S_ + s) * D_;
    float h0 = vals[0] * scale, h1 = vals[1] * scale;
    g_h[rowo + tid] = h0;
    g_h[rowo + tid + 256] = h1;
    split_store(h0, hh, hl, rowo + tid);
    split_store(h1, hh, hl, rowo + tid + 256);
}

// ---------------- bf16x3 tensor-core GEMM (pre-split operands) ------------------
#define ASTR 132
#define BSTR 68

__device__ __forceinline__ void mma_bf16(float* d, const unsigned* a, const unsigned* b) {
    asm volatile(
        "mma.sync.aligned.m16n8k16.row.col.f32.bf16.bf16.f32 "
        "{%0,%1,%2,%3},{%4,%5,%6,%7},{%8,%9},{%0,%1,%2,%3};"
        : "+f"(d[0]), "+f"(d[1]), "+f"(d[2]), "+f"(d[3])
        : "r"(a[0]), "r"(a[1]), "r"(a[2]), "r"(a[3]), "r"(b[0]), "r"(b[1]));
}

__device__ __forceinline__ void gemm_core(const __nv_bfloat16* __restrict__ Ah,
                                          const __nv_bfloat16* __restrict__ Al,
                                          const uint32_t* __restrict__ Bhp,
                                          const uint32_t* __restrict__ Blp,
                                          float* __restrict__ C,
                                          int Mdim, int Kdim, int Ndim,
                                          int m0, int n0) {
    __shared__ __align__(16) uint2 As2[2][8][ASTR];
    __shared__ __align__(16) uint2 Bs2[2][8][BSTR];

    int tid = threadIdx.x;
    int lane = tid & 31, wid = tid >> 5;
    int wm = (wid & 3) * 32;
    int wn = (wid >> 2) * 32;
    int gid = lane >> 2, tig = lane & 3;
    int sA = (tig & 1) << 4;

    int rA = tid >> 1;
    int halfA = tid & 1;
    int kpB = tid >> 5;
    int ncB = lane * 2;
    int scB = ncB ^ ((kpB & 1) << 4);

    uint4 a_hi, a_lo;
    uint2 b_hi, b_lo;

    float acc[2][4][4];
#pragma unroll
    for (int i = 0; i < 2; i++)
#pragma unroll
        for (int j = 0; j < 4; j++)
#pragma unroll
            for (int k = 0; k < 4; k++) acc[i][j][k] = 0.f;

    int nk = Kdim >> 4;
    int growA = m0 + rA;
    bool aok = (growA < Mdim);
    size_t arow = (size_t)growA * Kdim;
    size_t brow = (size_t)kpB * Ndim + n0 + ncB;

    if (aok) {
        a_hi = *(const uint4*)(Ah + arow + halfA * 8);
        a_lo = *(const uint4*)(Al + arow + halfA * 8);
    } else {
        a_hi = make_uint4(0u, 0u, 0u, 0u); a_lo = a_hi;
    }
    b_hi = *(const uint2*)(Bhp + brow);
    b_lo = *(const uint2*)(Blp + brow);
    {
        int kp0 = halfA * 4;
        int rs0 = rA;
        int rs1 = rA ^ 16;
        As2[0][kp0 + 0][rs0] = make_uint2(a_hi.x, a_lo.x);
        As2[0][kp0 + 1][rs1] = make_uint2(a_hi.y, a_lo.y);
        As2[0][kp0 + 2][rs0] = make_uint2(a_hi.z, a_lo.z);
        As2[0][kp0 + 3][rs1] = make_uint2(a_hi.w, a_lo.w);
        *(uint4*)&Bs2[0][kpB][scB] = make_uint4(b_hi.x, b_lo.x, b_hi.y, b_lo.y);
    }
    __syncthreads();

    int cur = 0;
    for (int ks = 0; ks < nk; ks++) {
        int k0n = (ks + 1) << 4;
        if (ks + 1 < nk) {
            if (aok) {
                a_hi = *(const uint4*)(Ah + arow + k0n + halfA * 8);
                a_lo = *(const uint4*)(Al + arow + k0n + halfA * 8);
            }
            size_t bo = (size_t)(k0n >> 1) * Ndim;
            b_hi = *(const uint2*)(Bhp + bo + brow);
            b_lo = *(const uint2*)(Blp + bo + brow);
        }

        {
            unsigned afH[2][4], afL[2][4], bfH[4][2], bfL[4][2];
#pragma unroll
            for (int ma = 0; ma < 2; ma++) {
                int mr = wm + ma * 16 + gid;
                uint2 v0 = As2[cur][tig][mr ^ sA];
                uint2 v1 = As2[cur][tig][(mr + 8) ^ sA];
                uint2 v2 = As2[cur][tig + 4][mr ^ sA];
                uint2 v3 = As2[cur][tig + 4][(mr + 8) ^ sA];
                afH[ma][0] = v0.x; afL[ma][0] = v0.y;
                afH[ma][1] = v1.x; afL[ma][1] = v1.y;
                afH[ma][2] = v2.x; afL[ma][2] = v2.y;
                afH[ma][3] = v3.x; afL[ma][3] = v3.y;
            }
#pragma unroll
            for (int nb = 0; nb < 4; nb++) {
                int nc = wn + nb * 8 + gid;
                uint2 u0 = Bs2[cur][tig][nc ^ sA];
                uint2 u1 = Bs2[cur][tig + 4][nc ^ sA];
                bfH[nb][0] = u0.x; bfL[nb][0] = u0.y;
                bfH[nb][1] = u1.x; bfL[nb][1] = u1.y;
            }
#pragma unroll
            for (int ma = 0; ma < 2; ma++)
#pragma unroll
                for (int nb = 0; nb < 4; nb++) {
                    mma_bf16(acc[ma][nb], afL[ma], bfH[nb]);
                    mma_bf16(acc[ma][nb], afH[ma], bfL[nb]);
                    mma_bf16(acc[ma][nb], afH[ma], bfH[nb]);
                }
        }

        if (ks + 1 < nk) {
            int nxt = cur ^ 1;
            int kp0 = halfA * 4;
            int rs0 = rA;
            int rs1 = rA ^ 16;
            As2[nxt][kp0 + 0][rs0] = make_uint2(a_hi.x, a_lo.x);
            As2[nxt][kp0 + 1][rs1] = make_uint2(a_hi.y, a_lo.y);
            As2[nxt][kp0 + 2][rs0] = make_uint2(a_hi.z, a_lo.z);
            As2[nxt][kp0 + 3][rs1] = make_uint2(a_hi.w, a_lo.w);
            *(uint4*)&Bs2[nxt][kpB][scB] = make_uint4(b_hi.x, b_lo.x, b_hi.y, b_lo.y);
        }
        __syncthreads();
        cur ^= 1;
    }

#pragma unroll
    for (int ma = 0; ma < 2; ma++) {
#pragma unroll
        for (int nb = 0; nb < 4; nb++) {
            int row = m0 + wm + ma * 16 + gid;
            int col = n0 + wn + nb * 8 + tig * 2;
            if (row < Mdim) {
                float2 v = make_float2(acc[ma][nb][0], acc[ma][nb][1]);
                *(float2*)(C + (size_t)row * Ndim + col) = v;
            }
            if (row + 8 < Mdim) {
                float2 v = make_float2(acc[ma][nb][2], acc[ma][nb][3]);
                *(float2*)(C + (size_t)(row + 8) * Ndim + col) = v;
            }
        }
    }
}

__global__ __launch_bounds__(256, 2)
void gemm_kernel(const __nv_bfloat16* __restrict__ Ah, const __nv_bfloat16* __restrict__ Al,
                 const uint32_t* __restrict__ Bhp, const uint32_t* __restrict__ Blp,
                 float* __restrict__ C, int Mdim, int Kdim, int Ndim) {
    gemm_core(Ah, Al, Bhp, Blp, C, Mdim, Kdim, Ndim, blockIdx.y * 128, blockIdx.x * 64);
}

__global__ __launch_bounds__(256, 2)
void gemm_qkv_kernel(const __nv_bfloat16* __restrict__ Ah, const __nv_bfloat16* __restrict__ Al,
                     const uint32_t* __restrict__ whp, const uint32_t* __restrict__ wlp,
                     float* __restrict__ Cq, float* __restrict__ Ck, float* __restrict__ Cv) {
    int which = blockIdx.x >> 3;
    int n0 = (blockIdx.x & 7) * 64;
    const uint32_t* Bh = whp + (size_t)which * 131072;
    const uint32_t* Bl = wlp + (size_t)which * 131072;
    float* C = (which == 0) ? Cq : (which == 1) ? Ck : Cv;
    gemm_core(Ah, Al, Bh, Bl, C, M_, D_, D_, blockIdx.y * 128, n0);
}

// ---------------- q/k post: rope + transpose + cosine norm + scale -> bf16 ------
__global__ void qkpost_kernel(const float* __restrict__ qin, const float* __restrict__ kin,
                              __nv_bfloat16* __restrict__ qout, __nv_bfloat16* __restrict__ kout,
                              const float* __restrict__ sqk) {
    int transposed = blockIdx.y;
    const float* in = transposed ? kin : qin;
    __nv_bfloat16* out = transposed ? kout : qout;
    int wrk = blockIdx.x * 8 + (threadIdx.x >> 5);
    if (wrk >= B_ * LT_ * H_) return;
    int h = wrk % H_;
    int l = (wrk / H_) % LT_;
    int b = wrk / (H_ * LT_);
    int t = l / S_, s = l % S_;
    int j = threadIdx.x & 31;
    const float* row = in + ((size_t)(b * LT_) + l) * D_ + h * HD_;
    float x0 = row[2 * j], x1 = row[2 * j + 1];
    float y0 = x0, y1 = x1;
    if (t > 0) {
        float c = g_cos[(t - 1) * 32 + j], sn = g_sin[(t - 1) * 32 + j];
        y0 = x0 * c - x1 * sn;
        y1 = x0 * sn + x1 * c;
    }
    float ss = y0 * y0 + y1 * y1;
#pragma unroll
    for (int o = 16; o > 0; o >>= 1) ss += __shfl_xor_sync(0xffffffffu, ss, o);
    float scale = 0.125f / fmaxf(sqrtf(ss), 1e-6f);
    int lp = s * SEQ_PER_ + t;
    float o0 = y0 * scale * sqk[h * HD_ + 2 * j];
    float o1 = y1 * scale * sqk[h * HD_ + 2 * j + 1];
    if (transposed) {
        size_t base = (size_t)(b * H_ + h) * HD_ * LT_;
        out[base + (size_t)(2 * j) * LT_ + lp] = __float2bfloat16(o0);
        out[base + (size_t)(2 * j + 1) * LT_ + lp] = __float2bfloat16(o1);
    } else {
        __nv_bfloat16* orow = out + ((size_t)((b * H_ + h) * LT_) + lp) * HD_;
        orow[2 * j] = __float2bfloat16(o0);
        orow[2 * j + 1] = __float2bfloat16(o1);
    }
}

// ---------------- attention: 4 q rows, fused exp softmax, bf16x2 K loads -------
// Pass 1: each thread owns a PAIR of adjacent keys; one uint32 load = one dim
// for both keys (full-width coalescing, half the bytes of fp32).
__global__ void attn_kernel(const __nv_bfloat16* __restrict__ qp,
                            const __nv_bfloat16* __restrict__ kT,
                            const float* __restrict__ vv,
                            __nv_bfloat16* __restrict__ oh, __nv_bfloat16* __restrict__ ol) {
    int bid = blockIdx.x;
    int qt = bid % NQT_;
    int h = (bid / NQT_) % H_;
    int b = bid / (NQT_ * H_);
    int q0 = qt * QT_;
    int tid = threadIdx.x;
    int wid = tid >> 5, lane = tid & 31;

    __shared__ __align__(16) float qs[QT_][HD_];
    __shared__ float sc[QT_][LT_];
    __shared__ float wsum[QT_][8];
    __shared__ float part[8][QT_][HD_];
    __shared__ float sinv[QT_];

    for (int i = tid; i < QT_ * HD_; i += 256) {
        int qi = i >> 6, d = i & 63;
        int ql = q0 + qi;
        qs[qi][d] = (ql < LT_)
                    ? __bfloat162float(qp[((size_t)((b * H_ + h) * LT_) + ql) * HD_ + d])
                    : 0.f;
    }
    __syncthreads();

    const uint32_t* kb32 = (const uint32_t*)(kT + (size_t)(b * H_ + h) * HD_ * LT_);
    int tq0 = (q0 + 0) % SEQ_PER_;
    int tq1 = (q0 + 1) % SEQ_PER_;
    int tq2 = (q0 + 2) % SEQ_PER_;
    int tq3 = (q0 + 3) % SEQ_PER_;
    int tqa = (tq0 > tq1) ? tq0 : tq1;
    int tqb = (tq2 > tq3) ? tq2 : tq3;
    int tqmax = (tqa > tqb) ? tqa : tqb;

    float ls0 = 0.f, ls1 = 0.f, ls2 = 0.f, ls3 = 0.f;
    for (int kp = tid; kp < LTH_; kp += 256) {
        int k0 = kp * 2, k1 = k0 + 1;
        int tk0 = k0 % SEQ_PER_;
        int tk1 = k1 % SEQ_PER_;
        if (tk0 > tqmax && tk1 > tqmax) {
            sc[0][k0] = 0.f; sc[1][k0] = 0.f; sc[2][k0] = 0.f; sc[3][k0] = 0.f;
            sc[0][k1] = 0.f; sc[1][k1] = 0.f; sc[2][k1] = 0.f; sc[3][k1] = 0.f;
            continue;
        }
        float aX[QT_], aY[QT_];
#pragma unroll
        for (int qi = 0; qi < QT_; qi++) { aX[qi] = 0.f; aY[qi] = 0.f; }
#pragma unroll 4
        for (int d4 = 0; d4 < HD_; d4 += 4) {
#pragma unroll
            for (int dd = 0; dd < 4; dd++) {
                uint32_t w = kb32[(size_t)(d4 + dd) * LTH_ + kp];
                float2 kv = __bfloat1622float2(*(const __nv_bfloat162*)&w);
#pragma unroll
                for (int qi = 0; qi < QT_; qi++) {
                    float qv = qs[qi][d4 + dd];
                    aX[qi] += qv * kv.x;
                    aY[qi] += qv * kv.y;
                }
            }
        }
        float e;
        e = (tk0 <= tq0) ? expf(aX[0] * 8.f) : 0.f; sc[0][k0] = e; ls0 += e;
        e = (tk0 <= tq1) ? expf(aX[1] * 8.f) : 0.f; sc[1][k0] = e; ls1 += e;
        e = (tk0 <= tq2) ? expf(aX[2] * 8.f) : 0.f; sc[2][k0] = e; ls2 += e;
        e = (tk0 <= tq3) ? expf(aX[3] * 8.f) : 0.f; sc[3][k0] = e; ls3 += e;
        e = (tk1 <= tq0) ? expf(aY[0] * 8.f) : 0.f; sc[0][k1] = e; ls0 += e;
        e = (tk1 <= tq1) ? expf(aY[1] * 8.f) : 0.f; sc[1][k1] = e; ls1 += e;
        e = (tk1 <= tq2) ? expf(aY[2] * 8.f) : 0.f; sc[2][k1] = e; ls2 += e;
        e = (tk1 <= tq3) ? expf(aY[3] * 8.f) : 0.f; sc[3][k1] = e; ls3 += e;
    }
#pragma unroll
    for (int o = 16; o > 0; o >>= 1) {
        ls0 += __shfl_xor_sync(0xffffffffu, ls0, o);
        ls1 += __shfl_xor_sync(0xffffffffu, ls1, o);
        ls2 += __shfl_xor_sync(0xffffffffu, ls2, o);
        ls3 += __shfl_xor_sync(0xffffffffu, ls3, o);
    }
    if (lane == 0) {
        wsum[0][wid] = ls0; wsum[1][wid] = ls1;
        wsum[2][wid] = ls2; wsum[3][wid] = ls3;
    }
    __syncthreads();
    if (tid < 32) {
        int qi = tid >> 3, w = tid & 7;
        float v = wsum[qi][w];
        v += __shfl_xor_sync(0xffffffffu, v, 4);
        v += __shfl_xor_sync(0xffffffffu, v, 2);
        v += __shfl_xor_sync(0xffffffffu, v, 1);
        if (w == 0) sinv[qi] = 1.f / v;
    }
    __syncthreads();

    float acc[QT_][2] = {};
    const float* vbase = vv + (size_t)b * LT_ * D_ + h * HD_;
    for (int k = wid; k < LT_; k += 8) {
        float p0 = sc[0][k], p1 = sc[1][k], p2 = sc[2][k], p3 = sc[3][k];
        if (p0 == 0.f && p1 == 0.f && p2 == 0.f && p3 == 0.f) continue;
        float v0 = vbase[(size_t)k * D_ + lane];
        float v1 = vbase[(size_t)k * D_ + lane + 32];
        acc[0][0] += p0 * v0; acc[0][1] += p0 * v1;
        acc[1][0] += p1 * v0; acc[1][1] += p1 * v1;
        acc[2][0] += p2 * v0; acc[2][1] += p2 * v1;
        acc[3][0] += p3 * v0; acc[3][1] += p3 * v1;
    }
#pragma unroll
    for (int qi = 0; qi < QT_; qi++) {
        part[wid][qi][lane] = acc[qi][0];
        part[wid][qi][lane + 32] = acc[qi][1];
    }
    __syncthreads();
    {
        int qi = tid >> 6, d = tid & 63;
        float o = 0.f;
#pragma unroll
        for (int w = 0; w < 8; w++) o += part[w][qi][d];
        int ql = q0 + qi;
        if (ql < LT_) {
            size_t oidx = ((size_t)(b * LT_) + ql) * D_ + h * HD_ + d;
            split_store(o * sinv[qi], oh, ol, oidx);
        }
    }
}

// ---------------- residual: h = cn(h + eig*sqrt(D)*(cn(xa) - h)) (+ planes) ----
__global__ void resid_kernel(const float* __restrict__ xa, const float* __restrict__ eig,
                             __nv_bfloat16* __restrict__ hh, __nv_bfloat16* __restrict__ hl) {
    int row = blockIdx.x, tid = threadIdx.x;
    __shared__ float red[256];
    size_t off = (size_t)row * D_;
    float x0 = xa[off + tid], x1 = xa[off + tid + 256];
    red[tid] = x0 * x0 + x1 * x1;
    __syncthreads();
    for (int st = 128; st > 0; st >>= 1) { if (tid < st) red[tid] += red[tid + st]; __syncthreads(); }
    float s1 = 1.f / fmaxf(sqrtf(red[0]), 1e-6f);
    __syncthreads();
    float h0 = g_h[off + tid], h1 = g_h[off + tid + 256];
    float t0 = h0 + eig[tid] * SQRT_D * (x0 * s1 - h0);
    float t1 = h1 + eig[tid + 256] * SQRT_D * (x1 * s1 - h1);
    red[tid] = t0 * t0 + t1 * t1;
    __syncthreads();
    for (int st = 128; st > 0; st >>= 1) { if (tid < st) red[tid] += red[tid + st]; __syncthreads(); }
    float s2 = 1.f / fmaxf(sqrtf(red[0]), 1e-6f);
    float n0 = t0 * s2, n1 = t1 * s2;
    g_h[off + tid] = n0;
    g_h[off + tid + 256] = n1;
    split_store(n0, hh, hl, off + tid);
    split_store(n1, hh, hl, off + tid + 256);
}

// ---------------- FFN activation -> bf16 planes --------------------------------
__global__ void act_kernel(const float* __restrict__ g, const float* __restrict__ su,
                           const float* __restrict__ sv,
                           __nv_bfloat16* __restrict__ oh, __nv_bfloat16* __restrict__ ol) {
    int total = M_ * DFF_;
    for (int idx = blockIdx.x * blockDim.x + threadIdx.x; idx < total;
         idx += gridDim.x * blockDim.x) {
        int row = idx / DFF_, j = idx - row * DFF_;
        float u = g[(size_t)row * (2 * DFF_) + j];
        float v = g[(size_t)row * (2 * DFF_) + DFF_ + j];
        float vs = v * sv[j] * SQRT_D;
        float sig = 1.f / (1.f + expf(-vs));
        split_store(u * su[j] * vs * sig, oh, ol, idx);
    }
}

// ---------------- output head: out = h @ Wout * (s_z * sqrt(D)) ----------------
__global__ void out_kernel(const float* __restrict__ Wout, const float* __restrict__ s_z,
                           float* __restrict__ out) {
    int row = blockIdx.x, tid = threadIdx.x;
    __shared__ float hs[D_];
    hs[tid] = g_h[(size_t)row * D_ + tid];
    hs[tid + 256] = g_h[(size_t)row * D_ + tid + 256];
    __syncthreads();
    int w = tid >> 5, lane = tid & 31;
    if (w < P_) {
        float a = 0.f;
        for (int d = lane; d < D_; d += 32) a += hs[d] * Wout[d * P_ + w];
#pragma unroll
        for (int o = 16; o > 0; o >>= 1) a += __shfl_xor_sync(0xffffffffu, a, o);
        if (lane == 0) out[row * P_ + w] = a * s_z[w] * SQRT_D;
    }
}

// ---------------- host driver --------------------------------------------------
extern "C" void kernel_launch(void* const* d_in, const int* in_sizes, int n_in,
                              void* d_out, int out_size) {
    (void)in_sizes; (void)n_in; (void)out_size;
    const float* x        = (const float*)d_in[0];
    const int*   sep      = (const int*)  d_in[1];
    const int*   tick     = (const int*)  d_in[2];
    const float* sep_emb  = (const float*)d_in[3];
    const float* tick_emb = (const float*)d_in[4];
    const float* shared_W = (const float*)d_in[5];
    const float* unique_W = (const float*)d_in[6];
    const float* Wq       = (const float*)d_in[7];
    const float* Wk       = (const float*)d_in[8];
    const float* Wv       = (const float*)d_in[9];
    const float* Wo       = (const float*)d_in[10];
    const float* s_qk     = (const float*)d_in[11];
    const float* Win      = (const float*)d_in[12];
    const float* Wff      = (const float*)d_in[13];
    const float* s_u      = (const float*)d_in[14];
    const float* s_v      = (const float*)d_in[15];
    const float* eigen_a  = (const float*)d_in[16];
    const float* eigen_m  = (const float*)d_in[17];
    const float* Wout     = (const float*)d_in[18];
    const float* s_z      = (const float*)d_in[19];
    float* out = (float*)d_out;

    float *p_h, *p_q, *p_k, *p_v, *p_xa, *p_ffn;
    __nv_bfloat16 *p_qp, *p_kT, *p_ah, *p_al;
    uint32_t *p_wh, *p_wl;
    cudaGetSymbolAddress((void**)&p_h,  g_h);
    cudaGetSymbolAddress((void**)&p_q,  g_q);
    cudaGetSymbolAddress((void**)&p_k,  g_k);
    cudaGetSymbolAddress((void**)&p_v,  g_v);
    cudaGetSymbolAddress((void**)&p_qp, g_qp);
    cudaGetSymbolAddress((void**)&p_kT, g_kT);
    cudaGetSymbolAddress((void**)&p_xa, g_xa);
    cudaGetSymbolAddress((void**)&p_ffn, g_ffn);
    cudaGetSymbolAddress((void**)&p_ah, g_ah);
    cudaGetSymbolAddress((void**)&p_al, g_al);
    cudaGetSymbolAddress((void**)&p_wh, g_wh);
    cudaGetSymbolAddress((void**)&p_wl, g_wl);

    rope_init_kernel<<<32, 256>>>();
    split_w_all<<<1024, 256>>>(Wq,  p_wh, p_wl, 512, 512,  OFF_WQ);
    split_w_all<<<1024, 256>>>(Wk,  p_wh, p_wl, 512, 512,  OFF_WK);
    split_w_all<<<1024, 256>>>(Wv,  p_wh, p_wl, 512, 512,  OFF_WV);
    split_w_all<<<1024, 256>>>(Wo,  p_wh, p_wl, 512, 512,  OFF_WO);
    split_w_all<<<4096, 256>>>(Win, p_wh, p_wl, 512, 4096, OFF_WIN);
    split_w_all<<<4096, 256>>>(Wff, p_wh, p_wl, 2048, 512, OFF_WFF);

    embed_kernel<<<B_ * SEQ_PER_ * S_, 256>>>(x, sep, tick, sep_emb, tick_emb,
                                              shared_W, unique_W, p_ah, p_al);

    dim3 gqkv(24, (M_ + 127) / 128);
    dim3 g512(8, (M_ + 127) / 128);
    dim3 g4096(64, (M_ + 127) / 128);
    dim3 gqkpost((B_ * LT_ * H_ + 7) / 8, 2);

    for (int L = 0; L < NL_; L++) {
        size_t wo = (size_t)L * WPAIR_L;
        gemm_qkv_kernel<<<gqkv, 256>>>(p_ah, p_al, p_wh + wo + OFF_WQ, p_wl + wo + OFF_WQ,
                                       p_q, p_k, p_v);
        qkpost_kernel<<<gqkpost, 256>>>(p_q, p_k, p_qp, p_kT, s_qk + L * H_ * HD_);
        attn_kernel<<<B_ * H_ * NQT_, 256>>>(p_qp, p_kT, p_v, p_ah, p_al);
        gemm_kernel<<<g512, 256>>>(p_ah, p_al, p_wh + wo + OFF_WO, p_wl + wo + OFF_WO,
                                   p_xa, M_, D_, D_);
        resid_kernel<<<M_, 256>>>(p_xa, eigen_a + L * D_, p_ah, p_al);
        gemm_kernel<<<g4096, 256>>>(p_ah, p_al, p_wh + wo + OFF_WIN, p_wl + wo + OFF_WIN,
                                    p_ffn, M_, D_, 2 * DFF_);
        act_kernel<<<2048, 256>>>(p_ffn, s_u + L * DFF_, s_v + L * DFF_, p_ah, p_al);
        gemm_kernel<<<g512, 256>>>(p_ah, p_al, p_wh + wo + OFF_WFF, p_wl + wo + OFF_WFF,
                                   p_xa, M_, DFF_, 512);
        resid_kernel<<<M_, 256>>>(p_xa, eigen_m + L * D_, p_ah, p_al);
    }
    out_kernel<<<M_, 256>>>(Wout, s_z, out);
}